// round 1
// baseline (speedup 1.0000x reference)
#include <cuda_runtime.h>
#include <math.h>

#define Bn 8
#define Hn 128
#define Wn 128
#define Cn 128
#define HWn (Hn*Wn)          // 16384
#define CHWn (Cn*HWn)        // 2097152
#define TOTALn (Bn*CHWn)     // 16777216
#define PAD 132

// Scratch (c-major [B,C,H,W] layouts). __device__ globals: allocation-free.
__device__ float g_qt[TOTALn];
__device__ float g_kt[TOTALn];
__device__ float g_vt[TOTALn];
__device__ float g_ot[TOTALn];

// ---------------------------------------------------------------------------
// Transpose-load a 128x128 fp32 tile (row-major src) into dst[k][w] with row
// stride PAD. 4x4 register micro-transpose keeps global loads coalesced and
// smem stores vectorized.
// ---------------------------------------------------------------------------
__device__ __forceinline__ void load_transpose_128(const float* __restrict__ src,
                                                   float* __restrict__ dst, int tid)
{
#pragma unroll
    for (int it = 0; it < 4; ++it) {
        int idx = tid + it * 256;        // 0..1023
        int rg  = idx >> 5;              // 4-row group of src (0..31)
        int c4  = idx & 31;              // col quad (0..31)
        float4 r0 = *(const float4*)(src + (rg * 4 + 0) * 128 + c4 * 4);
        float4 r1 = *(const float4*)(src + (rg * 4 + 1) * 128 + c4 * 4);
        float4 r2 = *(const float4*)(src + (rg * 4 + 2) * 128 + c4 * 4);
        float4 r3 = *(const float4*)(src + (rg * 4 + 3) * 128 + c4 * 4);
        *(float4*)(dst + (c4 * 4 + 0) * PAD + rg * 4) = make_float4(r0.x, r1.x, r2.x, r3.x);
        *(float4*)(dst + (c4 * 4 + 1) * PAD + rg * 4) = make_float4(r0.y, r1.y, r2.y, r3.y);
        *(float4*)(dst + (c4 * 4 + 2) * PAD + rg * 4) = make_float4(r0.z, r1.z, r2.z, r3.z);
        *(float4*)(dst + (c4 * 4 + 3) * PAD + rg * 4) = make_float4(r0.w, r1.w, r2.w, r3.w);
    }
}

// ---------------------------------------------------------------------------
// Projection: Yt[b][c][h][w] = relu( sum_k X[b][h][w][k] * Wm[k][c] )
// One block per (b,h) row of 128 pixels (=w). Classic 8x8 register tile.
// ---------------------------------------------------------------------------
__global__ __launch_bounds__(256, 1)
void proj_kernel(const float* __restrict__ X, const float* __restrict__ Wm,
                 float* __restrict__ Yt)
{
    extern __shared__ float sm[];
    float* As = sm;                 // [128][PAD]  As[k][w]
    float* Bs = sm + 128 * PAD;     // [128][128]  Bs[k][c]

    const int b   = blockIdx.x >> 7;
    const int h   = blockIdx.x & 127;
    const int tid = threadIdx.y * 16 + threadIdx.x;
    const float* Xt = X + (b * HWn + h * Wn) * Cn;   // [w][k], 128x128

    load_transpose_128(Xt, As, tid);
#pragma unroll
    for (int it = 0; it < 16; ++it) {
        int idx = tid + it * 256;
        ((float4*)Bs)[idx] = ((const float4*)Wm)[idx];
    }
    __syncthreads();

    const int ro = threadIdx.y * 8;
    const int co = threadIdx.x * 8;
    float acc[8][8];
#pragma unroll
    for (int i = 0; i < 8; ++i)
#pragma unroll
        for (int j = 0; j < 8; ++j) acc[i][j] = 0.f;

#pragma unroll 4
    for (int k = 0; k < 128; ++k) {
        float4 a0 = *(const float4*)(As + k * PAD + ro);
        float4 a1 = *(const float4*)(As + k * PAD + ro + 4);
        float4 b0 = *(const float4*)(Bs + k * 128 + co);
        float4 b1 = *(const float4*)(Bs + k * 128 + co + 4);
        float a[8] = {a0.x, a0.y, a0.z, a0.w, a1.x, a1.y, a1.z, a1.w};
        float bb[8] = {b0.x, b0.y, b0.z, b0.w, b1.x, b1.y, b1.z, b1.w};
#pragma unroll
        for (int i = 0; i < 8; ++i)
#pragma unroll
            for (int j = 0; j < 8; ++j) acc[i][j] += a[i] * bb[j];
    }

    // relu + store to c-major scratch: Yt[b][c][h][w], contiguous over w.
    float* out = Yt + b * CHWn + h * Wn;
#pragma unroll
    for (int j = 0; j < 8; ++j) {
        float* o = out + (co + j) * HWn + ro;
        *(float4*)(o)     = make_float4(fmaxf(acc[0][j], 0.f), fmaxf(acc[1][j], 0.f),
                                        fmaxf(acc[2][j], 0.f), fmaxf(acc[3][j], 0.f));
        *(float4*)(o + 4) = make_float4(fmaxf(acc[4][j], 0.f), fmaxf(acc[5][j], 0.f),
                                        fmaxf(acc[6][j], 0.f), fmaxf(acc[7][j], 0.f));
    }
}

// ---------------------------------------------------------------------------
// Attention per (b,c): S = q k^T (inner dim w), softmax rows, O = P v.
// q,k transposed into smem [w][h]; P reuses q's smem as [g][h].
// ---------------------------------------------------------------------------
__global__ __launch_bounds__(256, 1)
void attn_kernel(const float* __restrict__ qt, const float* __restrict__ kt,
                 const float* __restrict__ vt, float* __restrict__ ot,
                 const float* __restrict__ scale_p)
{
    extern __shared__ float sm[];
    float* qT  = sm;                      // [128][PAD]  q^T : qT[w][h]  (later reused as Ps[g][h])
    float* kT  = sm + 128 * PAD;          // [128][PAD]  k^T : kT[w][g]
    float* vs  = sm + 2 * 128 * PAD;      // [128][128]  v   : vs[g][w]
    float* red = vs + 128 * 128;          // [128][17]   reduction buffer

    const int b   = blockIdx.x >> 7;
    const int c   = blockIdx.x & 127;
    const int tid = threadIdx.y * 16 + threadIdx.x;
    const int base = b * CHWn + c * HWn;

    load_transpose_128(qt + base, qT, tid);
    load_transpose_128(kt + base, kT, tid);
#pragma unroll
    for (int it = 0; it < 16; ++it) {
        int idx = tid + it * 256;
        ((float4*)vs)[idx] = ((const float4*)(vt + base))[idx];
    }
    __syncthreads();

    const float sc = scale_p[0];
    const int ro = threadIdx.y * 8;       // h rows
    const int co = threadIdx.x * 8;       // g cols
    float acc[8][8];
#pragma unroll
    for (int i = 0; i < 8; ++i)
#pragma unroll
        for (int j = 0; j < 8; ++j) acc[i][j] = 0.f;

#pragma unroll 4
    for (int w = 0; w < 128; ++w) {
        float4 a0 = *(const float4*)(qT + w * PAD + ro);
        float4 a1 = *(const float4*)(qT + w * PAD + ro + 4);
        float4 b0 = *(const float4*)(kT + w * PAD + co);
        float4 b1 = *(const float4*)(kT + w * PAD + co + 4);
        float a[8]  = {a0.x, a0.y, a0.z, a0.w, a1.x, a1.y, a1.z, a1.w};
        float bb[8] = {b0.x, b0.y, b0.z, b0.w, b1.x, b1.y, b1.z, b1.w};
#pragma unroll
        for (int i = 0; i < 8; ++i)
#pragma unroll
            for (int j = 0; j < 8; ++j) acc[i][j] += a[i] * bb[j];
    }

    // scale
#pragma unroll
    for (int i = 0; i < 8; ++i)
#pragma unroll
        for (int j = 0; j < 8; ++j) acc[i][j] *= sc;

    // row max
    float rmax[8], rinv[8];
#pragma unroll
    for (int i = 0; i < 8; ++i) {
        float m = acc[i][0];
#pragma unroll
        for (int j = 1; j < 8; ++j) m = fmaxf(m, acc[i][j]);
        red[(ro + i) * 17 + threadIdx.x] = m;
    }
    __syncthreads();
#pragma unroll
    for (int i = 0; i < 8; ++i) {
        float m = red[(ro + i) * 17 + 0];
#pragma unroll
        for (int t = 1; t < 16; ++t) m = fmaxf(m, red[(ro + i) * 17 + t]);
        rmax[i] = m;
    }
    __syncthreads();
    // exp + row sum
#pragma unroll
    for (int i = 0; i < 8; ++i) {
        float s = 0.f;
#pragma unroll
        for (int j = 0; j < 8; ++j) {
            float e = __expf(acc[i][j] - rmax[i]);
            acc[i][j] = e;
            s += e;
        }
        red[(ro + i) * 17 + threadIdx.x] = s;
    }
    __syncthreads();
#pragma unroll
    for (int i = 0; i < 8; ++i) {
        float s = 0.f;
#pragma unroll
        for (int t = 0; t < 16; ++t) s += red[(ro + i) * 17 + t];
        rinv[i] = 1.f / s;
    }
    __syncthreads();   // everyone done with qT (S loop) and red reads

    // write normalized P into qT's smem as Ps[g][h]
    float* Ps = qT;
#pragma unroll
    for (int j = 0; j < 8; ++j) {
        *(float4*)(Ps + (co + j) * PAD + ro) =
            make_float4(acc[0][j] * rinv[0], acc[1][j] * rinv[1],
                        acc[2][j] * rinv[2], acc[3][j] * rinv[3]);
        *(float4*)(Ps + (co + j) * PAD + ro + 4) =
            make_float4(acc[4][j] * rinv[4], acc[5][j] * rinv[5],
                        acc[6][j] * rinv[6], acc[7][j] * rinv[7]);
    }
    __syncthreads();

    // O = P v  (rows h = ro.., cols w = co..)
#pragma unroll
    for (int i = 0; i < 8; ++i)
#pragma unroll
        for (int j = 0; j < 8; ++j) acc[i][j] = 0.f;

#pragma unroll 4
    for (int g = 0; g < 128; ++g) {
        float4 a0 = *(const float4*)(Ps + g * PAD + ro);
        float4 a1 = *(const float4*)(Ps + g * PAD + ro + 4);
        float4 b0 = *(const float4*)(vs + g * 128 + co);
        float4 b1 = *(const float4*)(vs + g * 128 + co + 4);
        float a[8]  = {a0.x, a0.y, a0.z, a0.w, a1.x, a1.y, a1.z, a1.w};
        float bb[8] = {b0.x, b0.y, b0.z, b0.w, b1.x, b1.y, b1.z, b1.w};
#pragma unroll
        for (int i = 0; i < 8; ++i)
#pragma unroll
            for (int j = 0; j < 8; ++j) acc[i][j] += a[i] * bb[j];
    }

    float* og = ot + base;
#pragma unroll
    for (int i = 0; i < 8; ++i) {
        *(float4*)(og + (ro + i) * 128 + co) =
            make_float4(acc[i][0], acc[i][1], acc[i][2], acc[i][3]);
        *(float4*)(og + (ro + i) * 128 + co + 4) =
            make_float4(acc[i][4], acc[i][5], acc[i][6], acc[i][7]);
    }
}

// ---------------------------------------------------------------------------
// Epilogue: g = sigmoid(o @ Ws + bs); BN affine; out = x1 + x2 * g
// o is read k-major from [B,C,H,W] scratch (no transpose needed).
// ---------------------------------------------------------------------------
__global__ __launch_bounds__(256, 1)
void epi_kernel(const float* __restrict__ ot,
                const float* __restrict__ x1, const float* __restrict__ x2,
                const float* __restrict__ Ws, const float* __restrict__ bsv_p,
                const float* __restrict__ gamma, const float* __restrict__ beta,
                const float* __restrict__ mu, const float* __restrict__ var,
                float* __restrict__ out)
{
    extern __shared__ float sm[];
    float* As = sm;                // [128][128]  As[c][w]
    float* Bs = sm + 128 * 128;    // [128][128]  Ws[c][d]

    const int b   = blockIdx.x >> 7;
    const int h   = blockIdx.x & 127;
    const int tid = threadIdx.y * 16 + threadIdx.x;
    const float* og = ot + b * CHWn + h * Wn;   // + c*HWn + w

#pragma unroll
    for (int it = 0; it < 16; ++it) {
        int idx = tid + it * 256;
        int c  = idx >> 5;
        int w4 = idx & 31;
        ((float4*)As)[idx] = *(const float4*)(og + c * HWn + w4 * 4);
        ((float4*)Bs)[idx] = ((const float4*)Ws)[idx];
    }
    __syncthreads();

    const int ro = threadIdx.y * 8;   // w rows
    const int co = threadIdx.x * 8;   // d cols
    float acc[8][8];
#pragma unroll
    for (int i = 0; i < 8; ++i)
#pragma unroll
        for (int j = 0; j < 8; ++j) acc[i][j] = 0.f;

#pragma unroll 4
    for (int k = 0; k < 128; ++k) {
        float4 a0 = *(const float4*)(As + k * 128 + ro);
        float4 a1 = *(const float4*)(As + k * 128 + ro + 4);
        float4 b0 = *(const float4*)(Bs + k * 128 + co);
        float4 b1 = *(const float4*)(Bs + k * 128 + co + 4);
        float a[8]  = {a0.x, a0.y, a0.z, a0.w, a1.x, a1.y, a1.z, a1.w};
        float bb[8] = {b0.x, b0.y, b0.z, b0.w, b1.x, b1.y, b1.z, b1.w};
#pragma unroll
        for (int i = 0; i < 8; ++i)
#pragma unroll
            for (int j = 0; j < 8; ++j) acc[i][j] += a[i] * bb[j];
    }

    // per-channel params for this thread's 8 output channels
    float pb[8], pg[8], pbe[8], pmu[8], pinv[8];
#pragma unroll
    for (int j = 0; j < 8; ++j) {
        int d = co + j;
        pb[j]   = bsv_p[d];
        pg[j]   = gamma[d];
        pbe[j]  = beta[d];
        pmu[j]  = mu[d];
        pinv[j] = rsqrtf(var[d] + 1e-3f);
    }

    const int pbase = b * HWn + h * Wn + ro;   // pixel index of row i=0
#pragma unroll
    for (int i = 0; i < 8; ++i) {
        int a = (pbase + i) * Cn + co;
        float4 x1a = *(const float4*)(x1 + a);
        float4 x1b = *(const float4*)(x1 + a + 4);
        float4 x2a = *(const float4*)(x2 + a);
        float4 x2b = *(const float4*)(x2 + a + 4);
        float r[8];
#pragma unroll
        for (int j = 0; j < 8; ++j) {
            float z  = acc[i][j] + pb[j];
            float s  = 1.f / (1.f + __expf(-z));
            r[j]     = pg[j] * (s - pmu[j]) * pinv[j] + pbe[j];
        }
        *(float4*)(out + a) =
            make_float4(x1a.x + x2a.x * r[0], x1a.y + x2a.y * r[1],
                        x1a.z + x2a.z * r[2], x1a.w + x2a.w * r[3]);
        *(float4*)(out + a + 4) =
            make_float4(x1b.x + x2b.x * r[4], x1b.y + x2b.y * r[5],
                        x1b.z + x2b.z * r[6], x1b.w + x2b.w * r[7]);
    }
}

// ---------------------------------------------------------------------------
extern "C" void kernel_launch(void* const* d_in, const int* in_sizes, int n_in,
                              void* d_out, int out_size)
{
    const float* x1    = (const float*)d_in[0];
    const float* x2    = (const float*)d_in[1];
    const float* Wq    = (const float*)d_in[2];
    const float* Wk    = (const float*)d_in[3];
    const float* Wv    = (const float*)d_in[4];
    const float* Ws    = (const float*)d_in[5];
    const float* bs    = (const float*)d_in[6];
    const float* scale = (const float*)d_in[7];
    const float* gamma = (const float*)d_in[8];
    const float* beta  = (const float*)d_in[9];
    const float* mu    = (const float*)d_in[10];
    const float* var   = (const float*)d_in[11];
    float* out = (float*)d_out;

    float *qt, *kt, *vt, *ot;
    cudaGetSymbolAddress((void**)&qt, g_qt);
    cudaGetSymbolAddress((void**)&kt, g_kt);
    cudaGetSymbolAddress((void**)&vt, g_vt);
    cudaGetSymbolAddress((void**)&ot, g_ot);

    const int smem_proj = (128 * PAD + 128 * 128) * 4;
    const int smem_attn = (2 * 128 * PAD + 128 * 128 + 128 * 17) * 4;
    const int smem_epi  = (2 * 128 * 128) * 4;
    cudaFuncSetAttribute(proj_kernel, cudaFuncAttributeMaxDynamicSharedMemorySize, smem_proj);
    cudaFuncSetAttribute(attn_kernel, cudaFuncAttributeMaxDynamicSharedMemorySize, smem_attn);
    cudaFuncSetAttribute(epi_kernel,  cudaFuncAttributeMaxDynamicSharedMemorySize, smem_epi);

    dim3 blk(16, 16);
    proj_kernel<<<1024, blk, smem_proj>>>(x1, Wq, qt);
    proj_kernel<<<1024, blk, smem_proj>>>(x1, Wk, kt);
    proj_kernel<<<1024, blk, smem_proj>>>(x2, Wv, vt);
    attn_kernel<<<1024, blk, smem_attn>>>(qt, kt, vt, ot, scale);
    epi_kernel<<<1024, blk, smem_epi>>>(ot, x1, x2, Ws, bs, gamma, beta, mu, var, out);
}

// round 2
// speedup vs baseline: 1.0017x; 1.0017x over previous
#include <cuda_runtime.h>
#include <math.h>

#define Bn 8
#define Hn 128
#define Wn 128
#define Cn 128
#define HWn (Hn*Wn)          // 16384
#define CHWn (Cn*HWn)        // 2097152
#define TOTALn (Bn*CHWn)     // 16777216
#define PAD 132

// Scratch (c-major [B,C,H,W] layouts). __device__ globals: allocation-free.
__device__ float g_qt[TOTALn];
__device__ float g_kt[TOTALn];
__device__ float g_vt[TOTALn];
__device__ float g_ot[TOTALn];

// ---------------------------------------------------------------------------
// Transpose-load a 128x128 fp32 tile (row-major src) into dst[k][w] with row
// stride PAD. 4x4 register micro-transpose keeps global loads coalesced and
// smem stores vectorized.
// ---------------------------------------------------------------------------
__device__ __forceinline__ void load_transpose_128(const float* __restrict__ src,
                                                   float* __restrict__ dst, int tid)
{
#pragma unroll
    for (int it = 0; it < 4; ++it) {
        int idx = tid + it * 256;        // 0..1023
        int rg  = idx >> 5;              // 4-row group of src (0..31)
        int c4  = idx & 31;              // col quad (0..31)
        float4 r0 = *(const float4*)(src + (rg * 4 + 0) * 128 + c4 * 4);
        float4 r1 = *(const float4*)(src + (rg * 4 + 1) * 128 + c4 * 4);
        float4 r2 = *(const float4*)(src + (rg * 4 + 2) * 128 + c4 * 4);
        float4 r3 = *(const float4*)(src + (rg * 4 + 3) * 128 + c4 * 4);
        *(float4*)(dst + (c4 * 4 + 0) * PAD + rg * 4) = make_float4(r0.x, r1.x, r2.x, r3.x);
        *(float4*)(dst + (c4 * 4 + 1) * PAD + rg * 4) = make_float4(r0.y, r1.y, r2.y, r3.y);
        *(float4*)(dst + (c4 * 4 + 2) * PAD + rg * 4) = make_float4(r0.z, r1.z, r2.z, r3.z);
        *(float4*)(dst + (c4 * 4 + 3) * PAD + rg * 4) = make_float4(r0.w, r1.w, r2.w, r3.w);
    }
}

// ---------------------------------------------------------------------------
// Projection: Yt[b][c][h][w] = relu( sum_k X[b][h][w][k] * Wm[k][c] )
// One block per (b,h) row of 128 pixels (=w). Classic 8x8 register tile.
// ---------------------------------------------------------------------------
__global__ __launch_bounds__(256, 1)
void proj_kernel(const float* __restrict__ X, const float* __restrict__ Wm,
                 float* __restrict__ Yt)
{
    extern __shared__ float sm[];
    float* As = sm;                 // [128][PAD]  As[k][w]
    float* Bs = sm + 128 * PAD;     // [128][128]  Bs[k][c]

    const int b   = blockIdx.x >> 7;
    const int h   = blockIdx.x & 127;
    const int tid = threadIdx.y * 16 + threadIdx.x;
    const float* Xt = X + (b * HWn + h * Wn) * Cn;   // [w][k], 128x128

    load_transpose_128(Xt, As, tid);
#pragma unroll
    for (int it = 0; it < 16; ++it) {
        int idx = tid + it * 256;
        ((float4*)Bs)[idx] = ((const float4*)Wm)[idx];
    }
    __syncthreads();

    const int ro = threadIdx.y * 8;
    const int co = threadIdx.x * 8;
    float acc[8][8];
#pragma unroll
    for (int i = 0; i < 8; ++i)
#pragma unroll
        for (int j = 0; j < 8; ++j) acc[i][j] = 0.f;

#pragma unroll 4
    for (int k = 0; k < 128; ++k) {
        float4 a0 = *(const float4*)(As + k * PAD + ro);
        float4 a1 = *(const float4*)(As + k * PAD + ro + 4);
        float4 b0 = *(const float4*)(Bs + k * 128 + co);
        float4 b1 = *(const float4*)(Bs + k * 128 + co + 4);
        float a[8] = {a0.x, a0.y, a0.z, a0.w, a1.x, a1.y, a1.z, a1.w};
        float bb[8] = {b0.x, b0.y, b0.z, b0.w, b1.x, b1.y, b1.z, b1.w};
#pragma unroll
        for (int i = 0; i < 8; ++i)
#pragma unroll
            for (int j = 0; j < 8; ++j) acc[i][j] += a[i] * bb[j];
    }

    // relu + store to c-major scratch: Yt[b][c][h][w], contiguous over w.
    float* out = Yt + b * CHWn + h * Wn;
#pragma unroll
    for (int j = 0; j < 8; ++j) {
        float* o = out + (co + j) * HWn + ro;
        *(float4*)(o)     = make_float4(fmaxf(acc[0][j], 0.f), fmaxf(acc[1][j], 0.f),
                                        fmaxf(acc[2][j], 0.f), fmaxf(acc[3][j], 0.f));
        *(float4*)(o + 4) = make_float4(fmaxf(acc[4][j], 0.f), fmaxf(acc[5][j], 0.f),
                                        fmaxf(acc[6][j], 0.f), fmaxf(acc[7][j], 0.f));
    }
}

// ---------------------------------------------------------------------------
// Attention per (b,c): S = q k^T (inner dim w), softmax rows, O = P v.
// q,k transposed into smem [w][h]; P reuses q's smem as [g][h].
// ---------------------------------------------------------------------------
__global__ __launch_bounds__(256, 1)
void attn_kernel(const float* __restrict__ qt, const float* __restrict__ kt,
                 const float* __restrict__ vt, float* __restrict__ ot,
                 const float* __restrict__ scale_p)
{
    extern __shared__ float sm[];
    float* qT  = sm;                      // [128][PAD]  q^T : qT[w][h]  (later reused as Ps[g][h])
    float* kT  = sm + 128 * PAD;          // [128][PAD]  k^T : kT[w][g]
    float* vs  = sm + 2 * 128 * PAD;      // [128][128]  v   : vs[g][w]
    float* red = vs + 128 * 128;          // [128][17]   reduction buffer

    const int b   = blockIdx.x >> 7;
    const int c   = blockIdx.x & 127;
    const int tid = threadIdx.y * 16 + threadIdx.x;
    const int base = b * CHWn + c * HWn;

    load_transpose_128(qt + base, qT, tid);
    load_transpose_128(kt + base, kT, tid);
#pragma unroll
    for (int it = 0; it < 16; ++it) {
        int idx = tid + it * 256;
        ((float4*)vs)[idx] = ((const float4*)(vt + base))[idx];
    }
    __syncthreads();

    const float sc = scale_p[0];
    const int ro = threadIdx.y * 8;       // h rows
    const int co = threadIdx.x * 8;       // g cols
    float acc[8][8];
#pragma unroll
    for (int i = 0; i < 8; ++i)
#pragma unroll
        for (int j = 0; j < 8; ++j) acc[i][j] = 0.f;

#pragma unroll 4
    for (int w = 0; w < 128; ++w) {
        float4 a0 = *(const float4*)(qT + w * PAD + ro);
        float4 a1 = *(const float4*)(qT + w * PAD + ro + 4);
        float4 b0 = *(const float4*)(kT + w * PAD + co);
        float4 b1 = *(const float4*)(kT + w * PAD + co + 4);
        float a[8]  = {a0.x, a0.y, a0.z, a0.w, a1.x, a1.y, a1.z, a1.w};
        float bb[8] = {b0.x, b0.y, b0.z, b0.w, b1.x, b1.y, b1.z, b1.w};
#pragma unroll
        for (int i = 0; i < 8; ++i)
#pragma unroll
            for (int j = 0; j < 8; ++j) acc[i][j] += a[i] * bb[j];
    }

    // scale
#pragma unroll
    for (int i = 0; i < 8; ++i)
#pragma unroll
        for (int j = 0; j < 8; ++j) acc[i][j] *= sc;

    // row max
    float rmax[8], rinv[8];
#pragma unroll
    for (int i = 0; i < 8; ++i) {
        float m = acc[i][0];
#pragma unroll
        for (int j = 1; j < 8; ++j) m = fmaxf(m, acc[i][j]);
        red[(ro + i) * 17 + threadIdx.x] = m;
    }
    __syncthreads();
#pragma unroll
    for (int i = 0; i < 8; ++i) {
        float m = red[(ro + i) * 17 + 0];
#pragma unroll
        for (int t = 1; t < 16; ++t) m = fmaxf(m, red[(ro + i) * 17 + t]);
        rmax[i] = m;
    }
    __syncthreads();
    // exp + row sum
#pragma unroll
    for (int i = 0; i < 8; ++i) {
        float s = 0.f;
#pragma unroll
        for (int j = 0; j < 8; ++j) {
            float e = __expf(acc[i][j] - rmax[i]);
            acc[i][j] = e;
            s += e;
        }
        red[(ro + i) * 17 + threadIdx.x] = s;
    }
    __syncthreads();
#pragma unroll
    for (int i = 0; i < 8; ++i) {
        float s = 0.f;
#pragma unroll
        for (int t = 0; t < 16; ++t) s += red[(ro + i) * 17 + t];
        rinv[i] = 1.f / s;
    }
    __syncthreads();   // everyone done with qT (S loop) and red reads

    // write normalized P into qT's smem as Ps[g][h]
    float* Ps = qT;
#pragma unroll
    for (int j = 0; j < 8; ++j) {
        *(float4*)(Ps + (co + j) * PAD + ro) =
            make_float4(acc[0][j] * rinv[0], acc[1][j] * rinv[1],
                        acc[2][j] * rinv[2], acc[3][j] * rinv[3]);
        *(float4*)(Ps + (co + j) * PAD + ro + 4) =
            make_float4(acc[4][j] * rinv[4], acc[5][j] * rinv[5],
                        acc[6][j] * rinv[6], acc[7][j] * rinv[7]);
    }
    __syncthreads();

    // O = P v  (rows h = ro.., cols w = co..)
#pragma unroll
    for (int i = 0; i < 8; ++i)
#pragma unroll
        for (int j = 0; j < 8; ++j) acc[i][j] = 0.f;

#pragma unroll 4
    for (int g = 0; g < 128; ++g) {
        float4 a0 = *(const float4*)(Ps + g * PAD + ro);
        float4 a1 = *(const float4*)(Ps + g * PAD + ro + 4);
        float4 b0 = *(const float4*)(vs + g * 128 + co);
        float4 b1 = *(const float4*)(vs + g * 128 + co + 4);
        float a[8]  = {a0.x, a0.y, a0.z, a0.w, a1.x, a1.y, a1.z, a1.w};
        float bb[8] = {b0.x, b0.y, b0.z, b0.w, b1.x, b1.y, b1.z, b1.w};
#pragma unroll
        for (int i = 0; i < 8; ++i)
#pragma unroll
            for (int j = 0; j < 8; ++j) acc[i][j] += a[i] * bb[j];
    }

    float* og = ot + base;
#pragma unroll
    for (int i = 0; i < 8; ++i) {
        *(float4*)(og + (ro + i) * 128 + co) =
            make_float4(acc[i][0], acc[i][1], acc[i][2], acc[i][3]);
        *(float4*)(og + (ro + i) * 128 + co + 4) =
            make_float4(acc[i][4], acc[i][5], acc[i][6], acc[i][7]);
    }
}

// ---------------------------------------------------------------------------
// Epilogue: g = sigmoid(o @ Ws + bs); BN affine; out = x1 + x2 * g
// o is read k-major from [B,C,H,W] scratch (no transpose needed).
// ---------------------------------------------------------------------------
__global__ __launch_bounds__(256, 1)
void epi_kernel(const float* __restrict__ ot,
                const float* __restrict__ x1, const float* __restrict__ x2,
                const float* __restrict__ Ws, const float* __restrict__ bsv_p,
                const float* __restrict__ gamma, const float* __restrict__ beta,
                const float* __restrict__ mu, const float* __restrict__ var,
                float* __restrict__ out)
{
    extern __shared__ float sm[];
    float* As = sm;                // [128][128]  As[c][w]
    float* Bs = sm + 128 * 128;    // [128][128]  Ws[c][d]

    const int b   = blockIdx.x >> 7;
    const int h   = blockIdx.x & 127;
    const int tid = threadIdx.y * 16 + threadIdx.x;
    const float* og = ot + b * CHWn + h * Wn;   // + c*HWn + w

#pragma unroll
    for (int it = 0; it < 16; ++it) {
        int idx = tid + it * 256;
        int c  = idx >> 5;
        int w4 = idx & 31;
        ((float4*)As)[idx] = *(const float4*)(og + c * HWn + w4 * 4);
        ((float4*)Bs)[idx] = ((const float4*)Ws)[idx];
    }
    __syncthreads();

    const int ro = threadIdx.y * 8;   // w rows
    const int co = threadIdx.x * 8;   // d cols
    float acc[8][8];
#pragma unroll
    for (int i = 0; i < 8; ++i)
#pragma unroll
        for (int j = 0; j < 8; ++j) acc[i][j] = 0.f;

#pragma unroll 4
    for (int k = 0; k < 128; ++k) {
        float4 a0 = *(const float4*)(As + k * 128 + ro);
        float4 a1 = *(const float4*)(As + k * 128 + ro + 4);
        float4 b0 = *(const float4*)(Bs + k * 128 + co);
        float4 b1 = *(const float4*)(Bs + k * 128 + co + 4);
        float a[8]  = {a0.x, a0.y, a0.z, a0.w, a1.x, a1.y, a1.z, a1.w};
        float bb[8] = {b0.x, b0.y, b0.z, b0.w, b1.x, b1.y, b1.z, b1.w};
#pragma unroll
        for (int i = 0; i < 8; ++i)
#pragma unroll
            for (int j = 0; j < 8; ++j) acc[i][j] += a[i] * bb[j];
    }

    // per-channel params for this thread's 8 output channels
    float pb[8], pg[8], pbe[8], pmu[8], pinv[8];
#pragma unroll
    for (int j = 0; j < 8; ++j) {
        int d = co + j;
        pb[j]   = bsv_p[d];
        pg[j]   = gamma[d];
        pbe[j]  = beta[d];
        pmu[j]  = mu[d];
        pinv[j] = rsqrtf(var[d] + 1e-3f);
    }

    const int pbase = b * HWn + h * Wn + ro;   // pixel index of row i=0
#pragma unroll
    for (int i = 0; i < 8; ++i) {
        int a = (pbase + i) * Cn + co;
        float4 x1a = *(const float4*)(x1 + a);
        float4 x1b = *(const float4*)(x1 + a + 4);
        float4 x2a = *(const float4*)(x2 + a);
        float4 x2b = *(const float4*)(x2 + a + 4);
        float r[8];
#pragma unroll
        for (int j = 0; j < 8; ++j) {
            float z  = acc[i][j] + pb[j];
            float s  = 1.f / (1.f + __expf(-z));
            r[j]     = pg[j] * (s - pmu[j]) * pinv[j] + pbe[j];
        }
        *(float4*)(out + a) =
            make_float4(x1a.x + x2a.x * r[0], x1a.y + x2a.y * r[1],
                        x1a.z + x2a.z * r[2], x1a.w + x2a.w * r[3]);
        *(float4*)(out + a + 4) =
            make_float4(x1b.x + x2b.x * r[4], x1b.y + x2b.y * r[5],
                        x1b.z + x2b.z * r[6], x1b.w + x2b.w * r[7]);
    }
}

// ---------------------------------------------------------------------------
extern "C" void kernel_launch(void* const* d_in, const int* in_sizes, int n_in,
                              void* d_out, int out_size)
{
    const float* x1    = (const float*)d_in[0];
    const float* x2    = (const float*)d_in[1];
    const float* Wq    = (const float*)d_in[2];
    const float* Wk    = (const float*)d_in[3];
    const float* Wv    = (const float*)d_in[4];
    const float* Ws    = (const float*)d_in[5];
    const float* bs    = (const float*)d_in[6];
    const float* scale = (const float*)d_in[7];
    const float* gamma = (const float*)d_in[8];
    const float* beta  = (const float*)d_in[9];
    const float* mu    = (const float*)d_in[10];
    const float* var   = (const float*)d_in[11];
    float* out = (float*)d_out;

    float *qt, *kt, *vt, *ot;
    cudaGetSymbolAddress((void**)&qt, g_qt);
    cudaGetSymbolAddress((void**)&kt, g_kt);
    cudaGetSymbolAddress((void**)&vt, g_vt);
    cudaGetSymbolAddress((void**)&ot, g_ot);

    const int smem_proj = (128 * PAD + 128 * 128) * 4;
    const int smem_attn = (2 * 128 * PAD + 128 * 128 + 128 * 17) * 4;
    const int smem_epi  = (2 * 128 * 128) * 4;
    cudaFuncSetAttribute(proj_kernel, cudaFuncAttributeMaxDynamicSharedMemorySize, smem_proj);
    cudaFuncSetAttribute(attn_kernel, cudaFuncAttributeMaxDynamicSharedMemorySize, smem_attn);
    cudaFuncSetAttribute(epi_kernel,  cudaFuncAttributeMaxDynamicSharedMemorySize, smem_epi);

    dim3 blk(16, 16);
    proj_kernel<<<1024, blk, smem_proj>>>(x1, Wq, qt);
    proj_kernel<<<1024, blk, smem_proj>>>(x1, Wk, kt);
    proj_kernel<<<1024, blk, smem_proj>>>(x2, Wv, vt);
    attn_kernel<<<1024, blk, smem_attn>>>(qt, kt, vt, ot, scale);
    epi_kernel<<<1024, blk, smem_epi>>>(ot, x1, x2, Ws, bs, gamma, beta, mu, var, out);
}

// round 4
// speedup vs baseline: 3.5918x; 3.5857x over previous
#include <cuda_runtime.h>
#include <cuda_bf16.h>
#include <cstdint>

typedef __nv_bfloat16 bf16;
#define HWn 16384
#define CHWn 2097152
#define TOTALn 16777216
#define SRU 68               // smem tile row stride in u32 (136 bf16, 272B)
#define TILE_B (128 * SRU * 4)   // 34816 bytes per bf16 tile
#define OPAD 132             // f32 bounce row stride

__device__ bf16 g_q[TOTALn];
__device__ bf16 g_k[TOTALn];
__device__ bf16 g_v[TOTALn];
__device__ bf16 g_o[TOTALn];
__device__ bf16 g_Wt[4 * 16384];   // transposed weights, [d][k] bf16

// ---------------- helpers ----------------
__device__ __forceinline__ uint32_t smem_u32(const void* p) {
    uint32_t a;
    asm("{ .reg .u64 t; cvta.to.shared.u64 t, %1; cvt.u32.u64 %0, t; }" : "=r"(a) : "l"(p));
    return a;
}
__device__ __forceinline__ uint32_t pk2(float hi, float lo) {
    uint32_t r;
    asm("cvt.rn.bf16x2.f32 %0, %1, %2;" : "=r"(r) : "f"(hi), "f"(lo));
    return r;
}
__device__ __forceinline__ void ldsm4(uint32_t r[4], uint32_t addr) {
    asm volatile("ldmatrix.sync.aligned.m8n8.x4.shared.b16 {%0,%1,%2,%3}, [%4];"
        : "=r"(r[0]), "=r"(r[1]), "=r"(r[2]), "=r"(r[3]) : "r"(addr));
}
__device__ __forceinline__ void ldsm4t(uint32_t r[4], uint32_t addr) {
    asm volatile("ldmatrix.sync.aligned.m8n8.x4.trans.shared.b16 {%0,%1,%2,%3}, [%4];"
        : "=r"(r[0]), "=r"(r[1]), "=r"(r[2]), "=r"(r[3]) : "r"(addr));
}
__device__ __forceinline__ void mma16816(float c[4], const uint32_t a[4],
                                         uint32_t b0, uint32_t b1) {
    asm volatile("mma.sync.aligned.m16n8k16.row.col.f32.bf16.bf16.f32 "
        "{%0,%1,%2,%3},{%4,%5,%6,%7},{%8,%9},{%0,%1,%2,%3};"
        : "+f"(c[0]), "+f"(c[1]), "+f"(c[2]), "+f"(c[3])
        : "r"(a[0]), "r"(a[1]), "r"(a[2]), "r"(a[3]), "r"(b0), "r"(b1));
}

// A-operand ldmatrix address (non-trans, storage [m][k], 272B rows):
// row = mbase + (lane&15), kbyte = 16*(lane>>4) + 32*kc
__device__ __forceinline__ uint32_t a_addr(uint32_t base, int mbase, int lane) {
    return base + (uint32_t)(mbase + (lane & 15)) * 272u + (uint32_t)((lane >> 4) << 4);
}
// B-operand (non-trans, storage [n][k]): covers n-tiles 2ng,2ng+1, k-chunk kc
__device__ __forceinline__ uint32_t b_addr(uint32_t base, int lane) {
    int bn = (lane & 7) + (((lane >> 4) & 1) << 3);
    int bk = ((lane >> 3) & 1) << 4;
    return base + (uint32_t)bn * 272u + (uint32_t)bk;
}
// trans B (storage [k][n]) : r0=b0(nt0),r1=b1(nt0),r2=b0(nt1),r3=b1(nt1)
__device__ __forceinline__ uint32_t bt_addr(uint32_t base, int lane) {
    int kr = (lane & 7) + (((lane >> 3) & 1) << 3);
    int nc = ((lane >> 4) & 1) << 3;
    return base + (uint32_t)kr * 272u + (uint32_t)(nc << 1);
}
// trans A (storage [k][m]) : r0=a0,r1=a1,r2=a2,r3=a3
__device__ __forceinline__ uint32_t at_addr(uint32_t base, int mbase, int lane) {
    int kr = (lane & 7) + (((lane >> 4) & 1) << 3);
    int mc = mbase + (((lane >> 3) & 1) << 3);
    return base + (uint32_t)kr * 272u + (uint32_t)(mc << 1);
}

// ---------------- prep: W[k][d] f32 -> Wt[d][k] bf16 ----------------
__global__ void prep_w(const float* __restrict__ W0, const float* __restrict__ W1,
                       const float* __restrict__ W2, const float* __restrict__ W3)
{
    extern __shared__ float wsm[];                      // [128][129]
    const float* src = blockIdx.x == 0 ? W0 : blockIdx.x == 1 ? W1
                     : blockIdx.x == 2 ? W2 : W3;
    for (int i = threadIdx.x; i < 16384; i += 256) wsm[(i >> 7) * 129 + (i & 127)] = src[i];
    __syncthreads();
    uint32_t* dst = (uint32_t*)(g_Wt + blockIdx.x * 16384);
    for (int i = threadIdx.x; i < 8192; i += 256) {
        int d = i >> 6, kk = i & 63;
        dst[d * 64 + kk] = pk2(wsm[(2 * kk + 1) * 129 + d], wsm[2 * kk * 129 + d]);
    }
}

// ---------------- projection: relu(X @ W) -> c-major bf16 scratch ----------------
__global__ __launch_bounds__(256, 2)
void proj_kernel(const float* __restrict__ X, const bf16* __restrict__ Wt,
                 bf16* __restrict__ out)
{
    extern __shared__ char sm[];
    uint32_t* As = (uint32_t*)sm;                 // [128][SRU]  A[w][c]
    uint32_t* Bs = As + 128 * SRU;                // [128][SRU]  Wt[d][k]
    float*    Ob = (float*)sm;                    // reuse: [128][OPAD] (c,w)
    const int tid = threadIdx.x;
    const int b = blockIdx.x >> 7, h = blockIdx.x & 127;

    const float* src = X + (size_t)(b * HWn + h * 128) * 128;
#pragma unroll
    for (int i = 0; i < 16; ++i) {                // A: f32 -> bf16
        int idx = i * 256 + tid;
        int w = idx >> 5, q = idx & 31;
        float4 f = *(const float4*)(src + w * 128 + q * 4);
        As[w * SRU + 2 * q]     = pk2(f.y, f.x);
        As[w * SRU + 2 * q + 1] = pk2(f.w, f.z);
    }
    const uint4* wsrc = (const uint4*)Wt;
#pragma unroll
    for (int i = 0; i < 8; ++i) {                 // B copy
        int idx = i * 256 + tid;
        int d = idx >> 4, q = idx & 15;
        *(uint4*)(Bs + d * SRU + q * 4) = wsrc[idx];
    }
    __syncthreads();

    const int wid = tid >> 5, lane = tid & 31;
    const int g = lane >> 2, t = lane & 3;
    const uint32_t sa = smem_u32(As), sb = smem_u32(Bs);
    const uint32_t aAd = a_addr(sa, wid * 16, lane);
    const uint32_t bAd = b_addr(sb, lane);
    float acc[16][4];
#pragma unroll
    for (int n = 0; n < 16; ++n)
#pragma unroll
        for (int j = 0; j < 4; ++j) acc[n][j] = 0.f;

#pragma unroll
    for (int kc = 0; kc < 8; ++kc) {
        uint32_t a[4];
        ldsm4(a, aAd + kc * 32);
#pragma unroll
        for (int ng = 0; ng < 8; ++ng) {
            uint32_t bb[4];
            ldsm4(bb, bAd + (uint32_t)(ng * 16) * 272u + kc * 32);
            mma16816(acc[2 * ng],     a, bb[0], bb[1]);
            mma16816(acc[2 * ng + 1], a, bb[2], bb[3]);
        }
    }
    __syncthreads();

    const int r0 = wid * 16 + g;
#pragma unroll
    for (int nt = 0; nt < 16; ++nt) {             // bounce: Ob[c][w]
        int c = 8 * nt + 2 * t;
        Ob[c * OPAD + r0]           = acc[nt][0];
        Ob[(c + 1) * OPAD + r0]     = acc[nt][1];
        Ob[c * OPAD + r0 + 8]       = acc[nt][2];
        Ob[(c + 1) * OPAD + r0 + 8] = acc[nt][3];
    }
    __syncthreads();

    bf16* dst = out + (size_t)b * CHWn + h * 128;
#pragma unroll
    for (int i = 0; i < 32; ++i) {                // relu + pack + coalesced store
        int idx = i * 256 + tid;
        int c = idx >> 6, q = idx & 63;
        float lo = fmaxf(Ob[c * OPAD + 2 * q], 0.f);
        float hi = fmaxf(Ob[c * OPAD + 2 * q + 1], 0.f);
        *(uint32_t*)(dst + (size_t)c * HWn + 2 * q) = pk2(hi, lo);
    }
}

// ---------------- attention per (b,c) ----------------
__global__ __launch_bounds__(256, 2)
void attn_kernel(const float* __restrict__ scale_p)
{
    extern __shared__ char sm[];
    uint32_t* Qs = (uint32_t*)sm;                 // [128][SRU]  q[h][w]
    uint32_t* Ks = Qs + 128 * SRU;                // k[g][w]
    uint32_t* Vs = Ks + 128 * SRU;                // v[g][w]
    const int tid = threadIdx.x;
    const size_t base = (size_t)blockIdx.x * HWn;

    const uint4* qsrc = (const uint4*)(g_q + base);
    const uint4* ksrc = (const uint4*)(g_k + base);
    const uint4* vsrc = (const uint4*)(g_v + base);
#pragma unroll
    for (int i = 0; i < 8; ++i) {
        int idx = i * 256 + tid;
        int r = idx >> 4, q = idx & 15;
        *(uint4*)(Qs + r * SRU + q * 4) = qsrc[idx];
        *(uint4*)(Ks + r * SRU + q * 4) = ksrc[idx];
        *(uint4*)(Vs + r * SRU + q * 4) = vsrc[idx];
    }
    __syncthreads();

    const int wid = tid >> 5, lane = tid & 31;
    const int g = lane >> 2, t = lane & 3;
    const uint32_t aAd = a_addr(smem_u32(Qs), wid * 16, lane);
    const uint32_t bAd = b_addr(smem_u32(Ks), lane);
    const uint32_t vAd = bt_addr(smem_u32(Vs), lane);
    const float sc = scale_p[0];

    float acc[16][4];
#pragma unroll
    for (int n = 0; n < 16; ++n)
#pragma unroll
        for (int j = 0; j < 4; ++j) acc[n][j] = 0.f;
#pragma unroll
    for (int kc = 0; kc < 8; ++kc) {              // S = q k^T
        uint32_t a[4];
        ldsm4(a, aAd + kc * 32);
#pragma unroll
        for (int ng = 0; ng < 8; ++ng) {
            uint32_t bb[4];
            ldsm4(bb, bAd + (uint32_t)(ng * 16) * 272u + kc * 32);
            mma16816(acc[2 * ng],     a, bb[0], bb[1]);
            mma16816(acc[2 * ng + 1], a, bb[2], bb[3]);
        }
    }

    // softmax over cols (each thread: rows r0=g, r1=g+8; quad-lanes share rows)
    float m0 = -1e30f, m1 = -1e30f;
#pragma unroll
    for (int n = 0; n < 16; ++n) {
#pragma unroll
        for (int j = 0; j < 4; ++j) acc[n][j] *= sc;
        m0 = fmaxf(m0, fmaxf(acc[n][0], acc[n][1]));
        m1 = fmaxf(m1, fmaxf(acc[n][2], acc[n][3]));
    }
    m0 = fmaxf(m0, __shfl_xor_sync(0xffffffffu, m0, 1));
    m0 = fmaxf(m0, __shfl_xor_sync(0xffffffffu, m0, 2));
    m1 = fmaxf(m1, __shfl_xor_sync(0xffffffffu, m1, 1));
    m1 = fmaxf(m1, __shfl_xor_sync(0xffffffffu, m1, 2));
    float s0 = 0.f, s1 = 0.f;
#pragma unroll
    for (int n = 0; n < 16; ++n) {
        acc[n][0] = __expf(acc[n][0] - m0);
        acc[n][1] = __expf(acc[n][1] - m0);
        acc[n][2] = __expf(acc[n][2] - m1);
        acc[n][3] = __expf(acc[n][3] - m1);
        s0 += acc[n][0] + acc[n][1];
        s1 += acc[n][2] + acc[n][3];
    }
    s0 += __shfl_xor_sync(0xffffffffu, s0, 1);
    s0 += __shfl_xor_sync(0xffffffffu, s0, 2);
    s1 += __shfl_xor_sync(0xffffffffu, s1, 1);
    s1 += __shfl_xor_sync(0xffffffffu, s1, 2);
    const float r0i = 1.f / s0, r1i = 1.f / s1;

    uint32_t pa[8][4];                            // P as A-fragments (unnormalized)
#pragma unroll
    for (int kc = 0; kc < 8; ++kc) {
        pa[kc][0] = pk2(acc[2 * kc][1],     acc[2 * kc][0]);
        pa[kc][1] = pk2(acc[2 * kc][3],     acc[2 * kc][2]);
        pa[kc][2] = pk2(acc[2 * kc + 1][1], acc[2 * kc + 1][0]);
        pa[kc][3] = pk2(acc[2 * kc + 1][3], acc[2 * kc + 1][2]);
    }

    float acc2[16][4];
#pragma unroll
    for (int n = 0; n < 16; ++n)
#pragma unroll
        for (int j = 0; j < 4; ++j) acc2[n][j] = 0.f;
#pragma unroll
    for (int kc = 0; kc < 8; ++kc) {              // O = P v (v k-major via trans)
#pragma unroll
        for (int ng = 0; ng < 8; ++ng) {
            uint32_t bb[4];
            ldsm4t(bb, vAd + (uint32_t)(kc * 16) * 272u + (uint32_t)(ng * 16 * 2));
            mma16816(acc2[2 * ng],     pa[kc], bb[0], bb[1]);
            mma16816(acc2[2 * ng + 1], pa[kc], bb[2], bb[3]);
        }
    }

    bf16* od = g_o + base;
    const int row0 = wid * 16 + g;
#pragma unroll
    for (int nt = 0; nt < 16; ++nt) {
        int w = 8 * nt + 2 * t;
        *(uint32_t*)(od + row0 * 128 + w)       = pk2(acc2[nt][1] * r0i, acc2[nt][0] * r0i);
        *(uint32_t*)(od + (row0 + 8) * 128 + w) = pk2(acc2[nt][3] * r1i, acc2[nt][2] * r1i);
    }
}

// ---------------- epilogue ----------------
#define EP_PARAM 69632
__global__ __launch_bounds__(256, 2)
void epi_kernel(const float* __restrict__ x1, const float* __restrict__ x2,
                const bf16* __restrict__ Wt, const float* __restrict__ bsv,
                const float* __restrict__ gamma, const float* __restrict__ beta,
                const float* __restrict__ mu, const float* __restrict__ var,
                float* __restrict__ out)
{
    extern __shared__ char sm[];
    uint32_t* As = (uint32_t*)sm;                 // [128][SRU]  o[c][w] (k-major A)
    uint32_t* Bs = As + 128 * SRU;                // Wt[d][k]
    float*    Ob = (float*)sm;                    // reuse: [128][OPAD] (w,d)
    float*    pA = (float*)(sm + EP_PARAM);       // gamma*inv
    float*    pB = pA + 128;                      // beta - gamma*mu*inv
    float*    pC = pB + 128;                      // bias
    const int tid = threadIdx.x;
    const int b = blockIdx.x >> 7, h = blockIdx.x & 127;

    const bf16* osrc = g_o + (size_t)b * CHWn + h * 128;
#pragma unroll
    for (int i = 0; i < 8; ++i) {
        int idx = i * 256 + tid;
        int c = idx >> 4, q = idx & 15;
        *(uint4*)(As + c * SRU + q * 4) = *(const uint4*)(osrc + (size_t)c * HWn + q * 8);
    }
    const uint4* wsrc = (const uint4*)Wt;
#pragma unroll
    for (int i = 0; i < 8; ++i) {
        int idx = i * 256 + tid;
        int d = idx >> 4, q = idx & 15;
        *(uint4*)(Bs + d * SRU + q * 4) = wsrc[idx];
    }
    if (tid < 128) {
        float inv = rsqrtf(var[tid] + 1e-3f);
        pA[tid] = gamma[tid] * inv;
        pB[tid] = beta[tid] - gamma[tid] * mu[tid] * inv;
        pC[tid] = bsv[tid];
    }
    __syncthreads();

    const int wid = tid >> 5, lane = tid & 31;
    const int g = lane >> 2, t = lane & 3;
    const uint32_t aAd = at_addr(smem_u32(As), wid * 16, lane);
    const uint32_t bAd = b_addr(smem_u32(Bs), lane);
    float acc[16][4];
#pragma unroll
    for (int n = 0; n < 16; ++n)
#pragma unroll
        for (int j = 0; j < 4; ++j) acc[n][j] = 0.f;
#pragma unroll
    for (int kc = 0; kc < 8; ++kc) {
        uint32_t a[4];
        ldsm4t(a, aAd + (uint32_t)(kc * 16) * 272u);
#pragma unroll
        for (int ng = 0; ng < 8; ++ng) {
            uint32_t bb[4];
            ldsm4(bb, bAd + (uint32_t)(ng * 16) * 272u + kc * 32);
            mma16816(acc[2 * ng],     a, bb[0], bb[1]);
            mma16816(acc[2 * ng + 1], a, bb[2], bb[3]);
        }
    }
    __syncthreads();

    const int r0 = wid * 16 + g;
#pragma unroll
    for (int nt = 0; nt < 16; ++nt) {             // bounce: Ob[w][d]
        int d = 8 * nt + 2 * t;
        *(float2*)(Ob + r0 * OPAD + d)       = make_float2(acc[nt][0], acc[nt][1]);
        *(float2*)(Ob + (r0 + 8) * OPAD + d) = make_float2(acc[nt][2], acc[nt][3]);
    }
    __syncthreads();

    const size_t pbase = (size_t)(b * HWn + h * 128) * 128;
#pragma unroll
    for (int i = 0; i < 16; ++i) {
        int idx = i * 256 + tid;
        int w = idx >> 5, q = idx & 31;
        int d = q * 4;
        size_t a = pbase + (size_t)w * 128 + d;
        float4 xa = *(const float4*)(x1 + a);
        float4 xb = *(const float4*)(x2 + a);
        float r[4];
#pragma unroll
        for (int j = 0; j < 4; ++j) {
            float z = Ob[w * OPAD + d + j] + pC[d + j];
            float s = 1.f / (1.f + __expf(-z));
            r[j] = pA[d + j] * s + pB[d + j];
        }
        *(float4*)(out + a) = make_float4(xa.x + xb.x * r[0], xa.y + xb.y * r[1],
                                          xa.z + xb.z * r[2], xa.w + xb.w * r[3]);
    }
}

// ---------------------------------------------------------------------------
extern "C" void kernel_launch(void* const* d_in, const int* in_sizes, int n_in,
                              void* d_out, int out_size)
{
    const float* x1    = (const float*)d_in[0];
    const float* x2    = (const float*)d_in[1];
    const float* Wq    = (const float*)d_in[2];
    const float* Wk    = (const float*)d_in[3];
    const float* Wv    = (const float*)d_in[4];
    const float* Ws    = (const float*)d_in[5];
    const float* bs    = (const float*)d_in[6];
    const float* scale = (const float*)d_in[7];
    const float* gamma = (const float*)d_in[8];
    const float* beta  = (const float*)d_in[9];
    const float* mu    = (const float*)d_in[10];
    const float* var   = (const float*)d_in[11];
    float* out = (float*)d_out;

    bf16 *q, *k, *v, *wt;
    cudaGetSymbolAddress((void**)&q,  g_q);
    cudaGetSymbolAddress((void**)&k,  g_k);
    cudaGetSymbolAddress((void**)&v,  g_v);
    cudaGetSymbolAddress((void**)&wt, g_Wt);

    const int sm_prep = 128 * 129 * 4;            // 66048
    const int sm_proj = 2 * TILE_B;               // 69632 (>= bounce 67584)
    const int sm_attn = 3 * TILE_B;               // 104448
    const int sm_epi  = EP_PARAM + 3 * 128 * 4;   // 71168
    cudaFuncSetAttribute(prep_w,      cudaFuncAttributeMaxDynamicSharedMemorySize, sm_prep);
    cudaFuncSetAttribute(proj_kernel, cudaFuncAttributeMaxDynamicSharedMemorySize, sm_proj);
    cudaFuncSetAttribute(attn_kernel, cudaFuncAttributeMaxDynamicSharedMemorySize, sm_attn);
    cudaFuncSetAttribute(epi_kernel,  cudaFuncAttributeMaxDynamicSharedMemorySize, sm_epi);

    prep_w<<<4, 256, sm_prep>>>(Wq, Wk, Wv, Ws);
    proj_kernel<<<1024, 256, sm_proj>>>(x1, wt,             q);
    proj_kernel<<<1024, 256, sm_proj>>>(x1, wt + 16384,     k);
    proj_kernel<<<1024, 256, sm_proj>>>(x2, wt + 2 * 16384, v);
    attn_kernel<<<1024, 256, sm_attn>>>(scale);
    epi_kernel<<<1024, 256, sm_epi>>>(x1, x2, wt + 3 * 16384, bs, gamma, beta, mu, var, out);
}

// round 5
// speedup vs baseline: 3.8344x; 1.0675x over previous
#include <cuda_runtime.h>
#include <cuda_bf16.h>
#include <cstdint>

typedef __nv_bfloat16 bf16;
#define HWn 16384
#define CHWn 2097152
#define TOTALn 16777216
#define SRU 68               // smem tile row stride in u32 (136 bf16, 272B)
#define TILE_B (128 * SRU * 4)   // 34816 bytes per bf16 tile
#define BPAD 136             // bf16 bounce row stride (272B = 17 x 16B)
#define OPAD 132             // f32 bounce row stride (epi)

__device__ bf16 g_q[TOTALn];
__device__ bf16 g_k[TOTALn];
__device__ bf16 g_v[TOTALn];
__device__ bf16 g_o[TOTALn];
__device__ bf16 g_Wt[4 * 16384];   // transposed weights, [d][k] bf16

// ---------------- helpers ----------------
__device__ __forceinline__ uint32_t smem_u32(const void* p) {
    uint32_t a;
    asm("{ .reg .u64 t; cvta.to.shared.u64 t, %1; cvt.u32.u64 %0, t; }" : "=r"(a) : "l"(p));
    return a;
}
__device__ __forceinline__ uint32_t pk2(float hi, float lo) {
    uint32_t r;
    asm("cvt.rn.bf16x2.f32 %0, %1, %2;" : "=r"(r) : "f"(hi), "f"(lo));
    return r;
}
__device__ __forceinline__ void ldsm4(uint32_t r[4], uint32_t addr) {
    asm volatile("ldmatrix.sync.aligned.m8n8.x4.shared.b16 {%0,%1,%2,%3}, [%4];"
        : "=r"(r[0]), "=r"(r[1]), "=r"(r[2]), "=r"(r[3]) : "r"(addr));
}
__device__ __forceinline__ void ldsm4t(uint32_t r[4], uint32_t addr) {
    asm volatile("ldmatrix.sync.aligned.m8n8.x4.trans.shared.b16 {%0,%1,%2,%3}, [%4];"
        : "=r"(r[0]), "=r"(r[1]), "=r"(r[2]), "=r"(r[3]) : "r"(addr));
}
__device__ __forceinline__ void mma16816(float c[4], const uint32_t a[4],
                                         uint32_t b0, uint32_t b1) {
    asm volatile("mma.sync.aligned.m16n8k16.row.col.f32.bf16.bf16.f32 "
        "{%0,%1,%2,%3},{%4,%5,%6,%7},{%8,%9},{%0,%1,%2,%3};"
        : "+f"(c[0]), "+f"(c[1]), "+f"(c[2]), "+f"(c[3])
        : "r"(a[0]), "r"(a[1]), "r"(a[2]), "r"(a[3]), "r"(b0), "r"(b1));
}

// ldmatrix address helpers (272B rows)
__device__ __forceinline__ uint32_t a_addr(uint32_t base, int mbase, int lane) {
    return base + (uint32_t)(mbase + (lane & 15)) * 272u + (uint32_t)((lane >> 4) << 4);
}
__device__ __forceinline__ uint32_t b_addr(uint32_t base, int lane) {
    int bn = (lane & 7) + (((lane >> 4) & 1) << 3);
    int bk = ((lane >> 3) & 1) << 4;
    return base + (uint32_t)bn * 272u + (uint32_t)bk;
}
__device__ __forceinline__ uint32_t bt_addr(uint32_t base, int lane) {
    int kr = (lane & 7) + (((lane >> 3) & 1) << 3);
    int nc = ((lane >> 4) & 1) << 3;
    return base + (uint32_t)kr * 272u + (uint32_t)(nc << 1);
}
__device__ __forceinline__ uint32_t at_addr(uint32_t base, int mbase, int lane) {
    int kr = (lane & 7) + (((lane >> 4) & 1) << 3);
    int mc = mbase + (((lane >> 3) & 1) << 3);
    return base + (uint32_t)kr * 272u + (uint32_t)(mc << 1);
}

// 128x128 GEMM: acc[16][4] += A(smem) * B(smem)^T, warp slab 16x128
__device__ __forceinline__ void gemm128(float acc[16][4], uint32_t aAd, uint32_t bAd) {
#pragma unroll
    for (int n = 0; n < 16; ++n)
#pragma unroll
        for (int j = 0; j < 4; ++j) acc[n][j] = 0.f;
#pragma unroll
    for (int kc = 0; kc < 8; ++kc) {
        uint32_t a[4];
        ldsm4(a, aAd + kc * 32);
#pragma unroll
        for (int ng = 0; ng < 8; ++ng) {
            uint32_t bb[4];
            ldsm4(bb, bAd + (uint32_t)(ng * 16) * 272u + kc * 32);
            mma16816(acc[2 * ng],     a, bb[0], bb[1]);
            mma16816(acc[2 * ng + 1], a, bb[2], bb[3]);
        }
    }
}

// relu + bf16 bounce [c][w] (BPAD stride) + coalesced c-major store
__device__ __forceinline__ void bounce_store(float acc[16][4], bf16* Bb,
                                             bf16* dst, int tid) {
    const int wid = tid >> 5, lane = tid & 31;
    const int g = lane >> 2, t = lane & 3;
    const int r0 = wid * 16 + g;
    __syncthreads();                       // prior readers of this region done
#pragma unroll
    for (int nt = 0; nt < 16; ++nt) {
        int c = 8 * nt + 2 * t;
        Bb[c * BPAD + r0]           = __float2bfloat16(fmaxf(acc[nt][0], 0.f));
        Bb[(c + 1) * BPAD + r0]     = __float2bfloat16(fmaxf(acc[nt][1], 0.f));
        Bb[c * BPAD + r0 + 8]       = __float2bfloat16(fmaxf(acc[nt][2], 0.f));
        Bb[(c + 1) * BPAD + r0 + 8] = __float2bfloat16(fmaxf(acc[nt][3], 0.f));
    }
    __syncthreads();
#pragma unroll
    for (int i = 0; i < 8; ++i) {
        int idx = i * 256 + tid;
        int c = idx >> 4, q = idx & 15;
        *(uint4*)(dst + (size_t)c * HWn + q * 8) = *(uint4*)(Bb + c * BPAD + q * 8);
    }
}

// ---------------- prep: W[k][d] f32 -> Wt[d][k] bf16 ----------------
__global__ void prep_w(const float* __restrict__ W0, const float* __restrict__ W1,
                       const float* __restrict__ W2, const float* __restrict__ W3)
{
    extern __shared__ float wsm[];                      // [128][129]
    const float* src = blockIdx.x == 0 ? W0 : blockIdx.x == 1 ? W1
                     : blockIdx.x == 2 ? W2 : W3;
    for (int i = threadIdx.x; i < 16384; i += 256) wsm[(i >> 7) * 129 + (i & 127)] = src[i];
    __syncthreads();
    uint32_t* dst = (uint32_t*)(g_Wt + blockIdx.x * 16384);
    for (int i = threadIdx.x; i < 8192; i += 256) {
        int d = i >> 6, kk = i & 63;
        dst[d * 64 + kk] = pk2(wsm[(2 * kk + 1) * 129 + d], wsm[2 * kk * 129 + d]);
    }
}

// ---------------- fused projection ----------------
// blocks [0,1024): q AND k from one x1 stage.  blocks [1024,2048): v from x2.
__global__ __launch_bounds__(256, 2)
void proj_kernel(const float* __restrict__ x1, const float* __restrict__ x2,
                 const bf16* __restrict__ Wt)
{
    extern __shared__ char sm[];
    uint32_t* As = (uint32_t*)sm;                 // region0: A[w][k]
    uint32_t* R1 = As + 128 * SRU;                // region1: Wq tile, then bounce
    uint32_t* R2 = R1 + 128 * SRU;                // region2: Wk tile (or Wv)
    bf16*     Bb = (bf16*)R1;                     // bounce view
    const int tid = threadIdx.x;
    const bool isv = blockIdx.x >= 1024;
    const int bh = blockIdx.x & 1023;
    const int b = bh >> 7, h = bh & 127;

    const float* src = (isv ? x2 : x1) + (size_t)(b * HWn + h * 128) * 128;
#pragma unroll
    for (int i = 0; i < 16; ++i) {                // stage A: f32 -> bf16
        int idx = i * 256 + tid;
        int w = idx >> 5, q = idx & 31;
        float4 f = *(const float4*)(src + w * 128 + q * 4);
        As[w * SRU + 2 * q]     = pk2(f.y, f.x);
        As[w * SRU + 2 * q + 1] = pk2(f.w, f.z);
    }
    // B tiles: qk blocks load Wq->R1, Wk->R2;  v blocks load Wv->R2
    const uint4* w1 = (const uint4*)(Wt + (isv ? 2 * 16384 : 0));
    const uint4* w2 = (const uint4*)(Wt + (isv ? 2 * 16384 : 16384));
#pragma unroll
    for (int i = 0; i < 8; ++i) {
        int idx = i * 256 + tid;
        int d = idx >> 4, q = idx & 15;
        if (!isv) *(uint4*)(R1 + d * SRU + q * 4) = w1[idx];
        *(uint4*)(R2 + d * SRU + q * 4) = w2[idx];
    }
    __syncthreads();

    const int wid = tid >> 5, lane = tid & 31;
    const uint32_t aAd = a_addr(smem_u32(As), wid * 16, lane);
    float acc[16][4];

    if (isv) {
        gemm128(acc, aAd, b_addr(smem_u32(R2), lane));
        bounce_store(acc, Bb, g_v + (size_t)b * CHWn + h * 128, tid);
    } else {
        gemm128(acc, aAd, b_addr(smem_u32(R1), lane));
        bounce_store(acc, Bb, g_q + (size_t)b * CHWn + h * 128, tid);  // kills R1
        gemm128(acc, aAd, b_addr(smem_u32(R2), lane));                 // reads 0,2 only
        bounce_store(acc, Bb, g_k + (size_t)b * CHWn + h * 128, tid);
    }
}

// ---------------- attention per (b,c) ----------------
__global__ __launch_bounds__(256, 2)
void attn_kernel(const float* __restrict__ scale_p)
{
    extern __shared__ char sm[];
    uint32_t* Qs = (uint32_t*)sm;                 // q[h][w]
    uint32_t* Ks = Qs + 128 * SRU;                // k[g][w]
    uint32_t* Vs = Ks + 128 * SRU;                // v[g][w]
    const int tid = threadIdx.x;
    const size_t base = (size_t)blockIdx.x * HWn;

    const uint4* qsrc = (const uint4*)(g_q + base);
    const uint4* ksrc = (const uint4*)(g_k + base);
    const uint4* vsrc = (const uint4*)(g_v + base);
#pragma unroll
    for (int i = 0; i < 8; ++i) {
        int idx = i * 256 + tid;
        int r = idx >> 4, q = idx & 15;
        *(uint4*)(Qs + r * SRU + q * 4) = qsrc[idx];
        *(uint4*)(Ks + r * SRU + q * 4) = ksrc[idx];
        *(uint4*)(Vs + r * SRU + q * 4) = vsrc[idx];
    }
    __syncthreads();

    const int wid = tid >> 5, lane = tid & 31;
    const int g = lane >> 2, t = lane & 3;
    const uint32_t aAd = a_addr(smem_u32(Qs), wid * 16, lane);
    const uint32_t bAd = b_addr(smem_u32(Ks), lane);
    const uint32_t vAd = bt_addr(smem_u32(Vs), lane);
    const float sc = scale_p[0];

    float acc[16][4];
    gemm128(acc, aAd, bAd);                       // S = q k^T

    float m0 = -1e30f, m1 = -1e30f;
#pragma unroll
    for (int n = 0; n < 16; ++n) {
#pragma unroll
        for (int j = 0; j < 4; ++j) acc[n][j] *= sc;
        m0 = fmaxf(m0, fmaxf(acc[n][0], acc[n][1]));
        m1 = fmaxf(m1, fmaxf(acc[n][2], acc[n][3]));
    }
    m0 = fmaxf(m0, __shfl_xor_sync(0xffffffffu, m0, 1));
    m0 = fmaxf(m0, __shfl_xor_sync(0xffffffffu, m0, 2));
    m1 = fmaxf(m1, __shfl_xor_sync(0xffffffffu, m1, 1));
    m1 = fmaxf(m1, __shfl_xor_sync(0xffffffffu, m1, 2));
    float s0 = 0.f, s1 = 0.f;
#pragma unroll
    for (int n = 0; n < 16; ++n) {
        acc[n][0] = __expf(acc[n][0] - m0);
        acc[n][1] = __expf(acc[n][1] - m0);
        acc[n][2] = __expf(acc[n][2] - m1);
        acc[n][3] = __expf(acc[n][3] - m1);
        s0 += acc[n][0] + acc[n][1];
        s1 += acc[n][2] + acc[n][3];
    }
    s0 += __shfl_xor_sync(0xffffffffu, s0, 1);
    s0 += __shfl_xor_sync(0xffffffffu, s0, 2);
    s1 += __shfl_xor_sync(0xffffffffu, s1, 1);
    s1 += __shfl_xor_sync(0xffffffffu, s1, 2);
    const float r0i = 1.f / s0, r1i = 1.f / s1;

    uint32_t pa[8][4];
#pragma unroll
    for (int kc = 0; kc < 8; ++kc) {
        pa[kc][0] = pk2(acc[2 * kc][1],     acc[2 * kc][0]);
        pa[kc][1] = pk2(acc[2 * kc][3],     acc[2 * kc][2]);
        pa[kc][2] = pk2(acc[2 * kc + 1][1], acc[2 * kc + 1][0]);
        pa[kc][3] = pk2(acc[2 * kc + 1][3], acc[2 * kc + 1][2]);
    }

    float acc2[16][4];
#pragma unroll
    for (int n = 0; n < 16; ++n)
#pragma unroll
        for (int j = 0; j < 4; ++j) acc2[n][j] = 0.f;
#pragma unroll
    for (int kc = 0; kc < 8; ++kc) {              // O = P v
#pragma unroll
        for (int ng = 0; ng < 8; ++ng) {
            uint32_t bb[4];
            ldsm4t(bb, vAd + (uint32_t)(kc * 16) * 272u + (uint32_t)(ng * 16 * 2));
            mma16816(acc2[2 * ng],     pa[kc], bb[0], bb[1]);
            mma16816(acc2[2 * ng + 1], pa[kc], bb[2], bb[3]);
        }
    }

    bf16* od = g_o + base;
    const int row0 = wid * 16 + g;
#pragma unroll
    for (int nt = 0; nt < 16; ++nt) {
        int w = 8 * nt + 2 * t;
        *(uint32_t*)(od + row0 * 128 + w)       = pk2(acc2[nt][1] * r0i, acc2[nt][0] * r0i);
        *(uint32_t*)(od + (row0 + 8) * 128 + w) = pk2(acc2[nt][3] * r1i, acc2[nt][2] * r1i);
    }
}

// ---------------- epilogue ----------------
#define EP_PARAM 69632
__global__ __launch_bounds__(256, 2)
void epi_kernel(const float* __restrict__ x1, const float* __restrict__ x2,
                const bf16* __restrict__ Wt, const float* __restrict__ bsv,
                const float* __restrict__ gamma, const float* __restrict__ beta,
                const float* __restrict__ mu, const float* __restrict__ var,
                float* __restrict__ out)
{
    extern __shared__ char sm[];
    uint32_t* As = (uint32_t*)sm;                 // o[c][w] (k-major A)
    uint32_t* Bs = As + 128 * SRU;                // Wt[d][k]
    float*    Ob = (float*)sm;                    // reuse: [128][OPAD] (w,d)
    float*    pA = (float*)(sm + EP_PARAM);
    float*    pB = pA + 128;
    float*    pC = pB + 128;
    const int tid = threadIdx.x;
    const int b = blockIdx.x >> 7, h = blockIdx.x & 127;

    const bf16* osrc = g_o + (size_t)b * CHWn + h * 128;
#pragma unroll
    for (int i = 0; i < 8; ++i) {
        int idx = i * 256 + tid;
        int c = idx >> 4, q = idx & 15;
        *(uint4*)(As + c * SRU + q * 4) = *(const uint4*)(osrc + (size_t)c * HWn + q * 8);
    }
    const uint4* wsrc = (const uint4*)Wt;
#pragma unroll
    for (int i = 0; i < 8; ++i) {
        int idx = i * 256 + tid;
        int d = idx >> 4, q = idx & 15;
        *(uint4*)(Bs + d * SRU + q * 4) = wsrc[idx];
    }
    if (tid < 128) {
        float inv = rsqrtf(var[tid] + 1e-3f);
        pA[tid] = gamma[tid] * inv;
        pB[tid] = beta[tid] - gamma[tid] * mu[tid] * inv;
        pC[tid] = bsv[tid];
    }
    __syncthreads();

    const int wid = tid >> 5, lane = tid & 31;
    const int g = lane >> 2, t = lane & 3;
    const uint32_t aAd = at_addr(smem_u32(As), wid * 16, lane);
    const uint32_t bAd = b_addr(smem_u32(Bs), lane);
    float acc[16][4];
#pragma unroll
    for (int n = 0; n < 16; ++n)
#pragma unroll
        for (int j = 0; j < 4; ++j) acc[n][j] = 0.f;
#pragma unroll
    for (int kc = 0; kc < 8; ++kc) {
        uint32_t a[4];
        ldsm4t(a, aAd + (uint32_t)(kc * 16) * 272u);
#pragma unroll
        for (int ng = 0; ng < 8; ++ng) {
            uint32_t bb[4];
            ldsm4(bb, bAd + (uint32_t)(ng * 16) * 272u + kc * 32);
            mma16816(acc[2 * ng],     a, bb[0], bb[1]);
            mma16816(acc[2 * ng + 1], a, bb[2], bb[3]);
        }
    }
    __syncthreads();

    const int r0 = wid * 16 + g;
#pragma unroll
    for (int nt = 0; nt < 16; ++nt) {
        int d = 8 * nt + 2 * t;
        *(float2*)(Ob + r0 * OPAD + d)       = make_float2(acc[nt][0], acc[nt][1]);
        *(float2*)(Ob + (r0 + 8) * OPAD + d) = make_float2(acc[nt][2], acc[nt][3]);
    }
    __syncthreads();

    const size_t pbase = (size_t)(b * HWn + h * 128) * 128;
#pragma unroll
    for (int i = 0; i < 16; ++i) {
        int idx = i * 256 + tid;
        int w = idx >> 5, q = idx & 31;
        int d = q * 4;
        size_t a = pbase + (size_t)w * 128 + d;
        float4 xa = *(const float4*)(x1 + a);
        float4 xb = *(const float4*)(x2 + a);
        float r[4];
#pragma unroll
        for (int j = 0; j < 4; ++j) {
            float z = Ob[w * OPAD + d + j] + pC[d + j];
            float s = 1.f / (1.f + __expf(-z));
            r[j] = pA[d + j] * s + pB[d + j];
        }
        *(float4*)(out + a) = make_float4(xa.x + xb.x * r[0], xa.y + xb.y * r[1],
                                          xa.z + xb.z * r[2], xa.w + xb.w * r[3]);
    }
}

// ---------------------------------------------------------------------------
extern "C" void kernel_launch(void* const* d_in, const int* in_sizes, int n_in,
                              void* d_out, int out_size)
{
    const float* x1    = (const float*)d_in[0];
    const float* x2    = (const float*)d_in[1];
    const float* Wq    = (const float*)d_in[2];
    const float* Wk    = (const float*)d_in[3];
    const float* Wv    = (const float*)d_in[4];
    const float* Ws    = (const float*)d_in[5];
    const float* bs    = (const float*)d_in[6];
    const float* scale = (const float*)d_in[7];
    const float* gamma = (const float*)d_in[8];
    const float* beta  = (const float*)d_in[9];
    const float* mu    = (const float*)d_in[10];
    const float* var   = (const float*)d_in[11];
    float* out = (float*)d_out;

    bf16* wt;
    cudaGetSymbolAddress((void**)&wt, g_Wt);

    const int sm_prep = 128 * 129 * 4;            // 66048
    const int sm_proj = 3 * TILE_B;               // 104448
    const int sm_attn = 3 * TILE_B;               // 104448
    const int sm_epi  = EP_PARAM + 3 * 128 * 4;   // 71168
    cudaFuncSetAttribute(prep_w,      cudaFuncAttributeMaxDynamicSharedMemorySize, sm_prep);
    cudaFuncSetAttribute(proj_kernel, cudaFuncAttributeMaxDynamicSharedMemorySize, sm_proj);
    cudaFuncSetAttribute(attn_kernel, cudaFuncAttributeMaxDynamicSharedMemorySize, sm_attn);
    cudaFuncSetAttribute(epi_kernel,  cudaFuncAttributeMaxDynamicSharedMemorySize, sm_epi);

    prep_w<<<4, 256, sm_prep>>>(Wq, Wk, Wv, Ws);
    proj_kernel<<<2048, 256, sm_proj>>>(x1, x2, wt);
    attn_kernel<<<1024, 256, sm_attn>>>(scale);
    epi_kernel<<<1024, 256, sm_epi>>>(x1, x2, wt + 3 * 16384, bs, gamma, beta, mu, var, out);
}

// round 6
// speedup vs baseline: 4.0986x; 1.0689x over previous
#include <cuda_runtime.h>
#include <cuda_bf16.h>
#include <cstdint>

typedef __nv_bfloat16 bf16;
#define HWn 16384
#define CHWn 2097152
#define TOTALn 16777216
#define SRU 68               // smem tile row stride in u32 (136 bf16, 272B)
#define TILE_B (128 * SRU * 4)   // 34816 bytes per bf16 tile
#define BPAD 136             // bf16 bounce row stride
#define EPW 68               // epi per-warp f32 bounce row stride

__device__ bf16 g_q[TOTALn];
__device__ bf16 g_k[TOTALn];
__device__ bf16 g_v[TOTALn];
__device__ bf16 g_o[TOTALn];
__device__ bf16 g_Wt[4 * 16384];   // transposed weights, [d][k] bf16

// ---------------- helpers ----------------
__device__ __forceinline__ uint32_t smem_u32(const void* p) {
    uint32_t a;
    asm("{ .reg .u64 t; cvta.to.shared.u64 t, %1; cvt.u32.u64 %0, t; }" : "=r"(a) : "l"(p));
    return a;
}
__device__ __forceinline__ uint32_t pk2(float hi, float lo) {
    uint32_t r;
    asm("cvt.rn.bf16x2.f32 %0, %1, %2;" : "=r"(r) : "f"(hi), "f"(lo));
    return r;
}
__device__ __forceinline__ void ldsm4(uint32_t r[4], uint32_t addr) {
    asm volatile("ldmatrix.sync.aligned.m8n8.x4.shared.b16 {%0,%1,%2,%3}, [%4];"
        : "=r"(r[0]), "=r"(r[1]), "=r"(r[2]), "=r"(r[3]) : "r"(addr));
}
__device__ __forceinline__ void ldsm4t(uint32_t r[4], uint32_t addr) {
    asm volatile("ldmatrix.sync.aligned.m8n8.x4.trans.shared.b16 {%0,%1,%2,%3}, [%4];"
        : "=r"(r[0]), "=r"(r[1]), "=r"(r[2]), "=r"(r[3]) : "r"(addr));
}
__device__ __forceinline__ void mma16816(float c[4], const uint32_t a[4],
                                         uint32_t b0, uint32_t b1) {
    asm volatile("mma.sync.aligned.m16n8k16.row.col.f32.bf16.bf16.f32 "
        "{%0,%1,%2,%3},{%4,%5,%6,%7},{%8,%9},{%0,%1,%2,%3};"
        : "+f"(c[0]), "+f"(c[1]), "+f"(c[2]), "+f"(c[3])
        : "r"(a[0]), "r"(a[1]), "r"(a[2]), "r"(a[3]), "r"(b0), "r"(b1));
}

// ldmatrix address helpers (272B rows)
__device__ __forceinline__ uint32_t a_addr(uint32_t base, int mbase, int lane) {
    return base + (uint32_t)(mbase + (lane & 15)) * 272u + (uint32_t)((lane >> 4) << 4);
}
__device__ __forceinline__ uint32_t b_addr(uint32_t base, int lane) {
    int bn = (lane & 7) + (((lane >> 4) & 1) << 3);
    int bk = ((lane >> 3) & 1) << 4;
    return base + (uint32_t)bn * 272u + (uint32_t)bk;
}
__device__ __forceinline__ uint32_t bt_addr(uint32_t base, int lane) {
    int kr = (lane & 7) + (((lane >> 3) & 1) << 3);
    int nc = ((lane >> 4) & 1) << 3;
    return base + (uint32_t)kr * 272u + (uint32_t)(nc << 1);
}
__device__ __forceinline__ uint32_t at_addr(uint32_t base, int mbase, int lane) {
    int kr = (lane & 7) + (((lane >> 4) & 1) << 3);
    int mc = mbase + (((lane >> 3) & 1) << 3);
    return base + (uint32_t)kr * 272u + (uint32_t)(mc << 1);
}

// 16x64 warp-tile GEMM (A non-trans): acc[8][4], n-tile base = dh*4
__device__ __forceinline__ void gemm64(float acc[8][4], uint32_t aAd, uint32_t bAd, int dh) {
#pragma unroll
    for (int n = 0; n < 8; ++n)
#pragma unroll
        for (int j = 0; j < 4; ++j) acc[n][j] = 0.f;
#pragma unroll
    for (int kc = 0; kc < 8; ++kc) {
        uint32_t a[4];
        ldsm4(a, aAd + kc * 32);
#pragma unroll
        for (int ng = 0; ng < 4; ++ng) {
            uint32_t bb[4];
            ldsm4(bb, bAd + (uint32_t)((dh * 4 + ng) * 16) * 272u + kc * 32);
            mma16816(acc[2 * ng],     a, bb[0], bb[1]);
            mma16816(acc[2 * ng + 1], a, bb[2], bb[3]);
        }
    }
}

// relu + bf16 bounce [c][w] + coalesced c-major store (512 threads)
__device__ __forceinline__ void bounce_store512(float acc[8][4], bf16* Bb,
                                                bf16* dst, int tid) {
    const int wid = tid >> 5, lane = tid & 31;
    const int ws = wid >> 1, dh = wid & 1;
    const int g = lane >> 2, t = lane & 3;
    const int r0 = ws * 16 + g;
    __syncthreads();                       // prior readers of this region done
#pragma unroll
    for (int nt = 0; nt < 8; ++nt) {
        int c = dh * 64 + 8 * nt + 2 * t;
        Bb[c * BPAD + r0]           = __float2bfloat16(fmaxf(acc[nt][0], 0.f));
        Bb[(c + 1) * BPAD + r0]     = __float2bfloat16(fmaxf(acc[nt][1], 0.f));
        Bb[c * BPAD + r0 + 8]       = __float2bfloat16(fmaxf(acc[nt][2], 0.f));
        Bb[(c + 1) * BPAD + r0 + 8] = __float2bfloat16(fmaxf(acc[nt][3], 0.f));
    }
    __syncthreads();
#pragma unroll
    for (int i = 0; i < 4; ++i) {
        int idx = i * 512 + tid;
        int c = idx >> 4, q = idx & 15;
        *(uint4*)(dst + (size_t)c * HWn + q * 8) = *(uint4*)(Bb + c * BPAD + q * 8);
    }
}

// ---------------- prep: W[k][d] f32 -> Wt[d][k] bf16 ----------------
__global__ void prep_w(const float* __restrict__ W0, const float* __restrict__ W1,
                       const float* __restrict__ W2, const float* __restrict__ W3)
{
    extern __shared__ float wsm[];                      // [128][129]
    const float* src = blockIdx.x == 0 ? W0 : blockIdx.x == 1 ? W1
                     : blockIdx.x == 2 ? W2 : W3;
    for (int i = threadIdx.x; i < 16384; i += 256) wsm[(i >> 7) * 129 + (i & 127)] = src[i];
    __syncthreads();
    uint32_t* dst = (uint32_t*)(g_Wt + blockIdx.x * 16384);
    for (int i = threadIdx.x; i < 8192; i += 256) {
        int d = i >> 6, kk = i & 63;
        dst[d * 64 + kk] = pk2(wsm[(2 * kk + 1) * 129 + d], wsm[2 * kk * 129 + d]);
    }
}

// ---------------- fused projection (512 threads) ----------------
// blocks [0,1024): q AND k from one x1 stage.  blocks [1024,2048): v from x2.
__global__ __launch_bounds__(512, 2)
void proj_kernel(const float* __restrict__ x1, const float* __restrict__ x2,
                 const bf16* __restrict__ Wt)
{
    extern __shared__ char sm[];
    uint32_t* As = (uint32_t*)sm;                 // region0: A[w][k]
    uint32_t* R1 = As + 128 * SRU;                // region1: Wq tile, then bounce
    uint32_t* R2 = R1 + 128 * SRU;                // region2: Wk tile (or Wv)
    bf16*     Bb = (bf16*)R1;                     // bounce view
    const int tid = threadIdx.x;
    const bool isv = blockIdx.x >= 1024;
    const int bh = blockIdx.x & 1023;
    const int b = bh >> 7, h = bh & 127;

    const float* src = (isv ? x2 : x1) + (size_t)(b * HWn + h * 128) * 128;
#pragma unroll
    for (int i = 0; i < 8; ++i) {                 // stage A: f32 -> bf16
        int idx = i * 512 + tid;
        int w = idx >> 5, q = idx & 31;
        float4 f = *(const float4*)(src + w * 128 + q * 4);
        As[w * SRU + 2 * q]     = pk2(f.y, f.x);
        As[w * SRU + 2 * q + 1] = pk2(f.w, f.z);
    }
    const uint4* w1 = (const uint4*)(Wt + (isv ? 2 * 16384 : 0));
    const uint4* w2 = (const uint4*)(Wt + (isv ? 2 * 16384 : 16384));
#pragma unroll
    for (int i = 0; i < 4; ++i) {
        int idx = i * 512 + tid;
        int d = idx >> 4, q = idx & 15;
        if (!isv) *(uint4*)(R1 + d * SRU + q * 4) = w1[idx];
        *(uint4*)(R2 + d * SRU + q * 4) = w2[idx];
    }
    __syncthreads();

    const int wid = tid >> 5, lane = tid & 31;
    const int ws = wid >> 1, dh = wid & 1;
    const uint32_t aAd = a_addr(smem_u32(As), ws * 16, lane);
    float acc[8][4];

    if (isv) {
        gemm64(acc, aAd, b_addr(smem_u32(R2), lane), dh);
        bounce_store512(acc, Bb, g_v + (size_t)b * CHWn + h * 128, tid);
    } else {
        gemm64(acc, aAd, b_addr(smem_u32(R1), lane), dh);
        bounce_store512(acc, Bb, g_q + (size_t)b * CHWn + h * 128, tid);
        gemm64(acc, aAd, b_addr(smem_u32(R2), lane), dh);
        bounce_store512(acc, Bb, g_k + (size_t)b * CHWn + h * 128, tid);
    }
}

// ---------------- attention per (b,c) (unchanged, 256 threads) ----------------
__global__ __launch_bounds__(256, 2)
void attn_kernel(const float* __restrict__ scale_p)
{
    extern __shared__ char sm[];
    uint32_t* Qs = (uint32_t*)sm;
    uint32_t* Ks = Qs + 128 * SRU;
    uint32_t* Vs = Ks + 128 * SRU;
    const int tid = threadIdx.x;
    const size_t base = (size_t)blockIdx.x * HWn;

    const uint4* qsrc = (const uint4*)(g_q + base);
    const uint4* ksrc = (const uint4*)(g_k + base);
    const uint4* vsrc = (const uint4*)(g_v + base);
#pragma unroll
    for (int i = 0; i < 8; ++i) {
        int idx = i * 256 + tid;
        int r = idx >> 4, q = idx & 15;
        *(uint4*)(Qs + r * SRU + q * 4) = qsrc[idx];
        *(uint4*)(Ks + r * SRU + q * 4) = ksrc[idx];
        *(uint4*)(Vs + r * SRU + q * 4) = vsrc[idx];
    }
    __syncthreads();

    const int wid = tid >> 5, lane = tid & 31;
    const int g = lane >> 2, t = lane & 3;
    const uint32_t aAd = a_addr(smem_u32(Qs), wid * 16, lane);
    const uint32_t bAd = b_addr(smem_u32(Ks), lane);
    const uint32_t vAd = bt_addr(smem_u32(Vs), lane);
    const float sc = scale_p[0];

    float acc[16][4];
#pragma unroll
    for (int n = 0; n < 16; ++n)
#pragma unroll
        for (int j = 0; j < 4; ++j) acc[n][j] = 0.f;
#pragma unroll
    for (int kc = 0; kc < 8; ++kc) {              // S = q k^T
        uint32_t a[4];
        ldsm4(a, aAd + kc * 32);
#pragma unroll
        for (int ng = 0; ng < 8; ++ng) {
            uint32_t bb[4];
            ldsm4(bb, bAd + (uint32_t)(ng * 16) * 272u + kc * 32);
            mma16816(acc[2 * ng],     a, bb[0], bb[1]);
            mma16816(acc[2 * ng + 1], a, bb[2], bb[3]);
        }
    }

    float m0 = -1e30f, m1 = -1e30f;
#pragma unroll
    for (int n = 0; n < 16; ++n) {
#pragma unroll
        for (int j = 0; j < 4; ++j) acc[n][j] *= sc;
        m0 = fmaxf(m0, fmaxf(acc[n][0], acc[n][1]));
        m1 = fmaxf(m1, fmaxf(acc[n][2], acc[n][3]));
    }
    m0 = fmaxf(m0, __shfl_xor_sync(0xffffffffu, m0, 1));
    m0 = fmaxf(m0, __shfl_xor_sync(0xffffffffu, m0, 2));
    m1 = fmaxf(m1, __shfl_xor_sync(0xffffffffu, m1, 1));
    m1 = fmaxf(m1, __shfl_xor_sync(0xffffffffu, m1, 2));
    float s0 = 0.f, s1 = 0.f;
#pragma unroll
    for (int n = 0; n < 16; ++n) {
        acc[n][0] = __expf(acc[n][0] - m0);
        acc[n][1] = __expf(acc[n][1] - m0);
        acc[n][2] = __expf(acc[n][2] - m1);
        acc[n][3] = __expf(acc[n][3] - m1);
        s0 += acc[n][0] + acc[n][1];
        s1 += acc[n][2] + acc[n][3];
    }
    s0 += __shfl_xor_sync(0xffffffffu, s0, 1);
    s0 += __shfl_xor_sync(0xffffffffu, s0, 2);
    s1 += __shfl_xor_sync(0xffffffffu, s1, 1);
    s1 += __shfl_xor_sync(0xffffffffu, s1, 2);
    const float r0i = 1.f / s0, r1i = 1.f / s1;

    uint32_t pa[8][4];
#pragma unroll
    for (int kc = 0; kc < 8; ++kc) {
        pa[kc][0] = pk2(acc[2 * kc][1],     acc[2 * kc][0]);
        pa[kc][1] = pk2(acc[2 * kc][3],     acc[2 * kc][2]);
        pa[kc][2] = pk2(acc[2 * kc + 1][1], acc[2 * kc + 1][0]);
        pa[kc][3] = pk2(acc[2 * kc + 1][3], acc[2 * kc + 1][2]);
    }

    float acc2[16][4];
#pragma unroll
    for (int n = 0; n < 16; ++n)
#pragma unroll
        for (int j = 0; j < 4; ++j) acc2[n][j] = 0.f;
#pragma unroll
    for (int kc = 0; kc < 8; ++kc) {              // O = P v
#pragma unroll
        for (int ng = 0; ng < 8; ++ng) {
            uint32_t bb[4];
            ldsm4t(bb, vAd + (uint32_t)(kc * 16) * 272u + (uint32_t)(ng * 16 * 2));
            mma16816(acc2[2 * ng],     pa[kc], bb[0], bb[1]);
            mma16816(acc2[2 * ng + 1], pa[kc], bb[2], bb[3]);
        }
    }

    bf16* od = g_o + base;
    const int row0 = wid * 16 + g;
#pragma unroll
    for (int nt = 0; nt < 16; ++nt) {
        int w = 8 * nt + 2 * t;
        *(uint32_t*)(od + row0 * 128 + w)       = pk2(acc2[nt][1] * r0i, acc2[nt][0] * r0i);
        *(uint32_t*)(od + (row0 + 8) * 128 + w) = pk2(acc2[nt][3] * r1i, acc2[nt][2] * r1i);
    }
}

// ---------------- epilogue (512 threads, per-warp bounce) ----------------
#define EP_PARAM 69632
__global__ __launch_bounds__(512, 2)
void epi_kernel(const float* __restrict__ x1, const float* __restrict__ x2,
                const bf16* __restrict__ Wt, const float* __restrict__ bsv,
                const float* __restrict__ gamma, const float* __restrict__ beta,
                const float* __restrict__ mu, const float* __restrict__ var,
                float* __restrict__ out)
{
    extern __shared__ char sm[];
    uint32_t* As = (uint32_t*)sm;                 // o[c][w] (k-major A)
    uint32_t* Bs = As + 128 * SRU;                // Wt[d][k]
    float*    pA = (float*)(sm + EP_PARAM);
    float*    pB = pA + 128;
    float*    pC = pB + 128;
    const int tid = threadIdx.x;
    const int b = blockIdx.x >> 7, h = blockIdx.x & 127;

    const bf16* osrc = g_o + (size_t)b * CHWn + h * 128;
#pragma unroll
    for (int i = 0; i < 4; ++i) {
        int idx = i * 512 + tid;
        int c = idx >> 4, q = idx & 15;
        *(uint4*)(As + c * SRU + q * 4) = *(const uint4*)(osrc + (size_t)c * HWn + q * 8);
    }
    const uint4* wsrc = (const uint4*)Wt;
#pragma unroll
    for (int i = 0; i < 4; ++i) {
        int idx = i * 512 + tid;
        int d = idx >> 4, q = idx & 15;
        *(uint4*)(Bs + d * SRU + q * 4) = wsrc[idx];
    }
    if (tid < 128) {
        float inv = rsqrtf(var[tid] + 1e-3f);
        pA[tid] = gamma[tid] * inv;
        pB[tid] = beta[tid] - gamma[tid] * mu[tid] * inv;
        pC[tid] = bsv[tid];
    }
    __syncthreads();

    const int wid = tid >> 5, lane = tid & 31;
    const int ws = wid >> 1, dh = wid & 1;
    const int g = lane >> 2, t = lane & 3;
    const uint32_t aAd = at_addr(smem_u32(As), ws * 16, lane);
    const uint32_t bAd = b_addr(smem_u32(Bs), lane);
    float acc[8][4];
#pragma unroll
    for (int n = 0; n < 8; ++n)
#pragma unroll
        for (int j = 0; j < 4; ++j) acc[n][j] = 0.f;
#pragma unroll
    for (int kc = 0; kc < 8; ++kc) {
        uint32_t a[4];
        ldsm4t(a, aAd + (uint32_t)(kc * 16) * 272u);
#pragma unroll
        for (int ng = 0; ng < 4; ++ng) {
            uint32_t bb[4];
            ldsm4(bb, bAd + (uint32_t)((dh * 4 + ng) * 16) * 272u + kc * 32);
            mma16816(acc[2 * ng],     a, bb[0], bb[1]);
            mma16816(acc[2 * ng + 1], a, bb[2], bb[3]);
        }
    }
    __syncthreads();                              // As/Bs dead; reuse as bounce

    float* Ob = (float*)sm + wid * (16 * EPW);    // per-warp [16][EPW]
#pragma unroll
    for (int nt = 0; nt < 8; ++nt) {
        int ld = 8 * nt + 2 * t;
        Ob[g * EPW + ld]           = acc[nt][0];
        Ob[g * EPW + ld + 1]       = acc[nt][1];
        Ob[(g + 8) * EPW + ld]     = acc[nt][2];
        Ob[(g + 8) * EPW + ld + 1] = acc[nt][3];
    }
    __syncwarp();

    const size_t pbase = (size_t)(b * HWn + h * 128) * 128;
#pragma unroll
    for (int it = 0; it < 8; ++it) {
        int r2 = it * 2 + (lane >> 4);
        int cq = lane & 15;
        int w = ws * 16 + r2;
        int d = dh * 64 + cq * 4;
        size_t a = pbase + (size_t)w * 128 + d;
        float4 xa = *(const float4*)(x1 + a);
        float4 xb = *(const float4*)(x2 + a);
        float r[4];
#pragma unroll
        for (int j = 0; j < 4; ++j) {
            float z = Ob[r2 * EPW + cq * 4 + j] + pC[d + j];
            float s = 1.f / (1.f + __expf(-z));
            r[j] = pA[d + j] * s + pB[d + j];
        }
        *(float4*)(out + a) = make_float4(xa.x + xb.x * r[0], xa.y + xb.y * r[1],
                                          xa.z + xb.z * r[2], xa.w + xb.w * r[3]);
    }
}

// ---------------------------------------------------------------------------
extern "C" void kernel_launch(void* const* d_in, const int* in_sizes, int n_in,
                              void* d_out, int out_size)
{
    const float* x1    = (const float*)d_in[0];
    const float* x2    = (const float*)d_in[1];
    const float* Wq    = (const float*)d_in[2];
    const float* Wk    = (const float*)d_in[3];
    const float* Wv    = (const float*)d_in[4];
    const float* Ws    = (const float*)d_in[5];
    const float* bs    = (const float*)d_in[6];
    const float* scale = (const float*)d_in[7];
    const float* gamma = (const float*)d_in[8];
    const float* beta  = (const float*)d_in[9];
    const float* mu    = (const float*)d_in[10];
    const float* var   = (const float*)d_in[11];
    float* out = (float*)d_out;

    bf16* wt;
    cudaGetSymbolAddress((void**)&wt, g_Wt);

    const int sm_prep = 128 * 129 * 4;            // 66048
    const int sm_proj = 3 * TILE_B;               // 104448
    const int sm_attn = 3 * TILE_B;               // 104448
    const int sm_epi  = EP_PARAM + 3 * 128 * 4;   // 71168
    cudaFuncSetAttribute(prep_w,      cudaFuncAttributeMaxDynamicSharedMemorySize, sm_prep);
    cudaFuncSetAttribute(proj_kernel, cudaFuncAttributeMaxDynamicSharedMemorySize, sm_proj);
    cudaFuncSetAttribute(attn_kernel, cudaFuncAttributeMaxDynamicSharedMemorySize, sm_attn);
    cudaFuncSetAttribute(epi_kernel,  cudaFuncAttributeMaxDynamicSharedMemorySize, sm_epi);

    prep_w<<<4, 256, sm_prep>>>(Wq, Wk, Wv, Ws);
    proj_kernel<<<2048, 512, sm_proj>>>(x1, x2, wt);
    attn_kernel<<<1024, 256, sm_attn>>>(scale);
    epi_kernel<<<1024, 512, sm_epi>>>(x1, x2, wt + 3 * 16384, bs, gamma, beta, mu, var, out);
}